// round 1
// baseline (speedup 1.0000x reference)
#include <cuda_runtime.h>

// preds: [16,8,17,128,128] f32  -> flattened N=128, K=17, H=W=128
// gt:    [16,8,10,17,2]   f32  -> N=128, P=10, K=17, (x,y)
// out:   2 floats: total_within, total_across

#define N_FLAT 128
#define P_NUM 10
#define K_NUM 17
#define HW 128
#define PK (P_NUM * K_NUM)   // 170

__device__ float2 g_partial[N_FLAT];

__global__ __launch_bounds__(192) void group_loss_per_n(
    const float* __restrict__ preds,
    const float* __restrict__ gt)
{
    const int n = blockIdx.x;
    const int t = threadIdx.x;

    __shared__ float s_val[PK];
    __shared__ float s_msk[PK];
    __shared__ float s_embed[P_NUM];
    __shared__ float s_cnt[P_NUM];
    __shared__ float s_within[P_NUM];

    if (t < PK) {
        const int p = t / K_NUM;
        const int k = t - p * K_NUM;
        const int gbase = ((n * P_NUM + p) * K_NUM + k) * 2;
        const float gx = gt[gbase + 0];
        const float gy = gt[gbase + 1];
        // jnp.round = round half to even; rintf matches (default RN mode)
        const int x = (int)rintf(gx * 0.25f);
        const int y = (int)rintf(gy * 0.25f);
        const bool valid = (x >= 0) & (x < HW) & (y >= 0) & (y < HW);
        const int xc = min(max(x, 0), HW - 1);
        const int yc = min(max(y, 0), HW - 1);
        const float v = preds[((n * K_NUM + k) * HW + yc) * HW + xc];
        s_val[t] = v;
        s_msk[t] = valid ? 1.0f : 0.0f;
    }
    __syncthreads();

    if (t < P_NUM) {
        float sum = 0.0f, cnt = 0.0f;
        #pragma unroll
        for (int k = 0; k < K_NUM; k++) {
            sum += s_val[t * K_NUM + k] * s_msk[t * K_NUM + k];
            cnt += s_msk[t * K_NUM + k];
        }
        const float safe = fmaxf(cnt, 1.0f);
        const float e = sum / safe;
        float w = 0.0f;
        #pragma unroll
        for (int k = 0; k < K_NUM; k++) {
            const float d = s_val[t * K_NUM + k] - e;
            w += d * d * s_msk[t * K_NUM + k];
        }
        w /= safe;
        s_embed[t] = e;
        s_cnt[t] = cnt;
        s_within[t] = (cnt > 0.0f) ? w : 0.0f;
    }
    __syncthreads();

    if (t == 0) {
        float within = 0.0f;
        #pragma unroll
        for (int p = 0; p < P_NUM; p++) within += s_within[p];
        within *= (1.0f / (float)P_NUM);

        float hinge_sum = 0.0f, denom = 0.0f;
        #pragma unroll
        for (int i = 0; i < P_NUM; i++) {
            if (s_cnt[i] <= 0.0f) continue;
            #pragma unroll
            for (int j = 0; j < P_NUM; j++) {
                if (j == i || s_cnt[j] <= 0.0f) continue;
                const float diff = s_embed[j] - s_embed[i];
                hinge_sum += fmaxf(1.0f - fabsf(diff), 0.0f);
                denom += 1.0f;
            }
        }
        const float across = (denom > 0.0f) ? (hinge_sum / denom) : 0.0f;
        g_partial[n] = make_float2(within, across);
    }
}

__global__ __launch_bounds__(128) void group_loss_reduce(float* __restrict__ out)
{
    const int t = threadIdx.x;
    __shared__ float s_w[N_FLAT];
    __shared__ float s_a[N_FLAT];
    const float2 v = g_partial[t];
    s_w[t] = v.x;
    s_a[t] = v.y;
    __syncthreads();
    // deterministic tree reduction
    for (int s = N_FLAT / 2; s > 0; s >>= 1) {
        if (t < s) {
            s_w[t] += s_w[t + s];
            s_a[t] += s_a[t + s];
        }
        __syncthreads();
    }
    if (t == 0) {
        out[0] = s_w[0] * (1.0f / (float)N_FLAT);
        out[1] = s_a[0] * (1.0f / (float)N_FLAT);
    }
}

extern "C" void kernel_launch(void* const* d_in, const int* in_sizes, int n_in,
                              void* d_out, int out_size)
{
    const float* preds = (const float*)d_in[0];
    const float* gt    = (const float*)d_in[1];
    float* out = (float*)d_out;
    group_loss_per_n<<<N_FLAT, 192>>>(preds, gt);
    group_loss_reduce<<<1, N_FLAT>>>(out);
}

// round 2
// speedup vs baseline: 1.0037x; 1.0037x over previous
#include <cuda_runtime.h>

// preds: [16,8,17,128,128] f32  -> flattened N=128, K=17, H=W=128
// gt:    [16,8,10,17,2]   f32  -> N=128, P=10, K=17, (x,y)
// out:   2 floats: total_within, total_across

#define N_FLAT 128
#define P_NUM 10
#define K_NUM 17
#define HW 128
#define PK (P_NUM * K_NUM)   // 170

__device__ float2 g_partial[N_FLAT];
__device__ unsigned int g_count = 0;

__global__ __launch_bounds__(192) void group_loss_fused(
    const float* __restrict__ preds,
    const float* __restrict__ gt,
    float* __restrict__ out)
{
    const int n = blockIdx.x;
    const int t = threadIdx.x;

    __shared__ float s_val[PK];
    __shared__ float s_msk[PK];
    __shared__ float s_embed[P_NUM];
    __shared__ float s_cnt[P_NUM];
    __shared__ float s_within[P_NUM];
    __shared__ bool s_last;

    if (t < PK) {
        const int p = t / K_NUM;
        const int k = t - p * K_NUM;
        const float2 g = ((const float2*)gt)[(n * P_NUM + p) * K_NUM + k];
        // jnp.round = round half to even; rintf matches (default RN mode)
        const int x = (int)rintf(g.x * 0.25f);
        const int y = (int)rintf(g.y * 0.25f);
        const bool valid = (x >= 0) & (x < HW) & (y >= 0) & (y < HW);
        const int xc = min(max(x, 0), HW - 1);
        const int yc = min(max(y, 0), HW - 1);
        const float v = preds[((n * K_NUM + k) * HW + yc) * HW + xc];
        s_val[t] = v;
        s_msk[t] = valid ? 1.0f : 0.0f;
    }
    __syncthreads();

    if (t < P_NUM) {
        float sum = 0.0f, cnt = 0.0f;
        #pragma unroll
        for (int k = 0; k < K_NUM; k++) {
            sum += s_val[t * K_NUM + k] * s_msk[t * K_NUM + k];
            cnt += s_msk[t * K_NUM + k];
        }
        const float safe = fmaxf(cnt, 1.0f);
        const float e = sum / safe;
        float w = 0.0f;
        #pragma unroll
        for (int k = 0; k < K_NUM; k++) {
            const float d = s_val[t * K_NUM + k] - e;
            w += d * d * s_msk[t * K_NUM + k];
        }
        w /= safe;
        s_embed[t] = e;
        s_cnt[t] = cnt;
        s_within[t] = (cnt > 0.0f) ? w : 0.0f;
    }
    __syncthreads();

    if (t == 0) {
        float within = 0.0f;
        #pragma unroll
        for (int p = 0; p < P_NUM; p++) within += s_within[p];
        within *= (1.0f / (float)P_NUM);

        float hinge_sum = 0.0f, denom = 0.0f;
        #pragma unroll
        for (int i = 0; i < P_NUM; i++) {
            if (s_cnt[i] <= 0.0f) continue;
            #pragma unroll
            for (int j = 0; j < P_NUM; j++) {
                if (j == i || s_cnt[j] <= 0.0f) continue;
                const float diff = s_embed[j] - s_embed[i];
                hinge_sum += fmaxf(1.0f - fabsf(diff), 0.0f);
                denom += 1.0f;
            }
        }
        const float across = (denom > 0.0f) ? (hinge_sum / denom) : 0.0f;
        g_partial[n] = make_float2(within, across);

        // publish partial, then count this block as done
        __threadfence();
        const unsigned int prev = atomicAdd(&g_count, 1u);
        s_last = (prev == (unsigned int)(gridDim.x - 1));
    }
    __syncthreads();

    // last block to finish performs the deterministic final reduction
    if (s_last) {
        __shared__ float s_w[N_FLAT];
        __shared__ float s_a[N_FLAT];
        if (t < N_FLAT) {
            // g_partial writes are visible: every writer fenced before the
            // atomicAdd we observed, and the atomic orders at L2.
            const float2 v = g_partial[t];
            s_w[t] = v.x;
            s_a[t] = v.y;
        }
        __syncthreads();
        for (int s = N_FLAT / 2; s > 0; s >>= 1) {
            if (t < s) {
                s_w[t] += s_w[t + s];
                s_a[t] += s_a[t + s];
            }
            __syncthreads();
        }
        if (t == 0) {
            out[0] = s_w[0] * (1.0f / (float)N_FLAT);
            out[1] = s_a[0] * (1.0f / (float)N_FLAT);
            g_count = 0;   // reset for next graph replay
        }
    }
}

extern "C" void kernel_launch(void* const* d_in, const int* in_sizes, int n_in,
                              void* d_out, int out_size)
{
    const float* preds = (const float*)d_in[0];
    const float* gt    = (const float*)d_in[1];
    float* out = (float*)d_out;
    group_loss_fused<<<N_FLAT, 192>>>(preds, gt, out);
}